// round 12
// baseline (speedup 1.0000x reference)
#include <cuda_runtime.h>
#include <cuda_bf16.h>
#include <cstdint>

// ComplexAttention B=4, S=2048, DIM=1024 — split-bf16 mma.sync tensor-core port.
// R11: fragment double-buffering — all 24 ldsm per chunk issued before the 96
// mma, letting ptxas hide ldsm latency under HMMA issue (tensor was 50% duty).
#define B_ 4
#define S_ 2048
#define D_ 1024
#define M_ (B_ * S_)   // 8192
#define TD 2048        // 2*D

// GEMM tiling
#define BM 128
#define BN 128
#define BK 32
#define NSTAGE 4
#define ST_A_HI 0
#define ST_A_LO 10240
#define ST_B_HI 20480
#define ST_B_LO 30720
#define STAGE_SZ 40960
#define SMEM_TOTAL (NSTAGE * STAGE_SZ)   // 163840

// ---------------------------------------------------------------------------
// Scratch (__device__ globals; allocation-free rule)
// ---------------------------------------------------------------------------
__device__ __nv_bfloat16 g_Zhi[(size_t)M_ * TD];
__device__ __nv_bfloat16 g_Zlo[(size_t)M_ * TD];
__device__ __nv_bfloat16 g_Whi[(size_t)3 * TD * TD];   // 6144 x 2048
__device__ __nv_bfloat16 g_Wlo[(size_t)3 * TD * TD];
__device__ __nv_bfloat16 g_Qhi[(size_t)M_ * TD];
__device__ __nv_bfloat16 g_Qlo[(size_t)M_ * TD];
__device__ __nv_bfloat16 g_Khi[(size_t)M_ * TD];
__device__ __nv_bfloat16 g_Klo[(size_t)M_ * TD];
__device__ __nv_bfloat16 g_Vhi[(size_t)M_ * TD];       // natural [b*t][n]
__device__ __nv_bfloat16 g_Vlo[(size_t)M_ * TD];
__device__ float         g_P  [(size_t)B_ * S_ * S_];
__device__ __nv_bfloat16 g_Phi[(size_t)B_ * S_ * S_];
__device__ __nv_bfloat16 g_Plo[(size_t)B_ * S_ * S_];

// ---------------------------------------------------------------------------
// PTX helpers (sm_80-class only)
// ---------------------------------------------------------------------------
__device__ __forceinline__ uint32_t smem_u32(const void* p) {
    uint32_t a;
    asm("{ .reg .u64 t; cvta.to.shared.u64 t, %1; cvt.u32.u64 %0, t; }" : "=r"(a) : "l"(p));
    return a;
}
__device__ __forceinline__ void ldsm_x4(uint32_t* r, uint32_t addr) {
    asm volatile("ldmatrix.sync.aligned.m8n8.x4.shared.b16 {%0,%1,%2,%3}, [%4];"
        : "=r"(r[0]), "=r"(r[1]), "=r"(r[2]), "=r"(r[3]) : "r"(addr));
}
__device__ __forceinline__ void ldsm_x4_t(uint32_t* r, uint32_t addr) {
    asm volatile("ldmatrix.sync.aligned.m8n8.x4.trans.shared.b16 {%0,%1,%2,%3}, [%4];"
        : "=r"(r[0]), "=r"(r[1]), "=r"(r[2]), "=r"(r[3]) : "r"(addr));
}
__device__ __forceinline__ void mma_bf16(float* d, const uint32_t* a, const uint32_t* b) {
    asm volatile(
        "mma.sync.aligned.m16n8k16.row.col.f32.bf16.bf16.f32 "
        "{%0,%1,%2,%3}, {%4,%5,%6,%7}, {%8,%9}, {%0,%1,%2,%3};"
        : "+f"(d[0]), "+f"(d[1]), "+f"(d[2]), "+f"(d[3])
        : "r"(a[0]), "r"(a[1]), "r"(a[2]), "r"(a[3]), "r"(b[0]), "r"(b[1]));
}
#define CP_ASYNC16(dst, src) \
    asm volatile("cp.async.cg.shared.global [%0], [%1], 16;" :: "r"(dst), "l"(src) : "memory")
#define CP_COMMIT() asm volatile("cp.async.commit_group;" ::: "memory")
#define CP_WAITG2() asm volatile("cp.async.wait_group 2;" ::: "memory")

__device__ __forceinline__ uint32_t pack2(float a, float b) {
    uint16_t la = __bfloat16_as_ushort(__float2bfloat16(a));
    uint16_t lb = __bfloat16_as_ushort(__float2bfloat16(b));
    return (uint32_t)la | ((uint32_t)lb << 16);
}
__device__ __forceinline__ void split_bf(float x, float& h, float& l) {
    h = __bfloat162float(__float2bfloat16(x));
    l = x - h;
}

// ---------------------------------------------------------------------------
// Prep 1: Zcat = [zr|zi] split to bf16 hi/lo.
// ---------------------------------------------------------------------------
__global__ void __launch_bounds__(256) split_z_kernel(const float* __restrict__ zr,
                                                      const float* __restrict__ zi) {
    const int idx = blockIdx.x * 256 + threadIdx.x;
    const int m = idx >> 9, c4 = idx & 511;
    const float* src = (c4 < 256) ? (zr + (size_t)m * D_ + c4 * 4)
                                  : (zi + (size_t)m * D_ + (c4 - 256) * 4);
    float4 x = *(const float4*)src;
    float h0, h1, h2, h3, l0, l1, l2, l3;
    split_bf(x.x, h0, l0); split_bf(x.y, h1, l1);
    split_bf(x.z, h2, l2); split_bf(x.w, h3, l3);
    const size_t o = (size_t)m * TD + c4 * 4;
    *(uint2*)(g_Zhi + o) = make_uint2(pack2(h0, h1), pack2(h2, h3));
    *(uint2*)(g_Zlo + o) = make_uint2(pack2(l0, l1), pack2(l2, l3));
}

// ---------------------------------------------------------------------------
// Prep 2: Wcat [6144 x 2048] with signs, split bf16 hi/lo.
// ---------------------------------------------------------------------------
__global__ void __launch_bounds__(256) build_w_kernel(
    const float* __restrict__ wqr, const float* __restrict__ wqi,
    const float* __restrict__ wkr, const float* __restrict__ wki,
    const float* __restrict__ wvr, const float* __restrict__ wvi) {
    const int idx = blockIdx.x * 256 + threadIdx.x;
    const int gn = idx >> 9, c4 = idx & 511;
    const int pair = gn >> 11, is_imag = (gn >> 10) & 1, nn = gn & 1023;
    const float* wr = (pair == 0) ? wqr : (pair == 1) ? wkr : wvr;
    const float* wi = (pair == 0) ? wqi : (pair == 1) ? wki : wvi;
    const float* wl = is_imag ? wi : wr;
    const float* wh = is_imag ? wr : wi;
    float4 x;
    if (c4 < 256) {
        x = *(const float4*)(wl + (size_t)nn * D_ + c4 * 4);
    } else {
        x = *(const float4*)(wh + (size_t)nn * D_ + (c4 - 256) * 4);
        const float s = is_imag ? 1.0f : -1.0f;
        x.x *= s; x.y *= s; x.z *= s; x.w *= s;
    }
    float h0, h1, h2, h3, l0, l1, l2, l3;
    split_bf(x.x, h0, l0); split_bf(x.y, h1, l1);
    split_bf(x.z, h2, l2); split_bf(x.w, h3, l3);
    const size_t o = (size_t)gn * TD + c4 * 4;
    *(uint2*)(g_Whi + o) = make_uint2(pack2(h0, h1), pack2(h2, h3));
    *(uint2*)(g_Wlo + o) = make_uint2(pack2(l0, l1), pack2(l2, l3));
}

// ---------------------------------------------------------------------------
// Split-bf16 tensor-core GEMM. MODE: 0=proj  1=scores  2=PV
// 4-stage cp.async ring; one barrier per chunk; both ks fragment sets are
// loaded before any mma so ldsm latency hides under HMMA issue.
// ---------------------------------------------------------------------------
template <int MODE>
__global__ void __launch_bounds__(256, 1)
gemm_kernel(float* __restrict__ outp) {
    extern __shared__ char smem[];
    const uint32_t sbase = smem_u32(smem);
    const int tid = threadIdx.x;
    const int wid = tid >> 5, lane = tid & 31;
    const int wm = (wid & 3) * 32;        // warp row base within tile
    const int wn = (wid >> 2) * 64;       // warp col base within tile
    const int tr = lane >> 2, tc = lane & 3;

    int m0, n0, kend, b = 0;
    const __nv_bfloat16 *Ahi_, *Alo_, *Bhi_, *Blo_;
    if (MODE == 0) {
        m0 = blockIdx.y * BM; n0 = blockIdx.x * BN; kend = TD;
        Ahi_ = g_Zhi; Alo_ = g_Zlo; Bhi_ = g_Whi; Blo_ = g_Wlo;
    } else if (MODE == 1) {
        b = blockIdx.z;
        const int x = blockIdx.x;   // triangular: x -> (r, c), c <= r
        int r = (int)((sqrtf(8.0f * x + 1.0f) - 1.0f) * 0.5f);
        while ((r + 1) * (r + 2) / 2 <= x) r++;
        while (r * (r + 1) / 2 > x) r--;
        m0 = r * BM; n0 = (x - r * (r + 1) / 2) * BN;
        kend = TD;
        Ahi_ = g_Qhi + (size_t)b * S_ * TD; Alo_ = g_Qlo + (size_t)b * S_ * TD;
        Bhi_ = g_Khi + (size_t)b * S_ * TD; Blo_ = g_Klo + (size_t)b * S_ * TD;
    } else {
        b = blockIdx.z; m0 = blockIdx.y * BM; n0 = blockIdx.x * BN;
        kend = m0 + BM;                   // P zero beyond diagonal
        Ahi_ = g_Phi + (size_t)b * S_ * S_; Alo_ = g_Plo + (size_t)b * S_ * S_;
        Bhi_ = g_Vhi + (size_t)b * S_ * TD; Blo_ = g_Vlo + (size_t)b * S_ * TD;
    }

    const int nch = kend / BK;   // >= 4 in all modes

    auto load_chunk = [&](int c, int st) {
        const int k0 = c * BK;
        const uint32_t so = sbase + st * STAGE_SZ;
#pragma unroll
        for (int i = 0; i < 2; i++) {
            const int s = i * 256 + tid;
            const int row = s >> 2, ch = s & 3;
            const size_t go = (size_t)(m0 + row) * TD + k0 + ch * 8;
            const uint32_t dA = so + ST_A_HI + row * 80 + ch * 16;
            CP_ASYNC16(dA, Ahi_ + go);
            CP_ASYNC16(dA + (ST_A_LO - ST_A_HI), Alo_ + go);
        }
        if (MODE != 2) {
#pragma unroll
            for (int i = 0; i < 2; i++) {
                const int s = i * 256 + tid;
                const int row = s >> 2, ch = s & 3;
                const size_t go = (size_t)(n0 + row) * TD + k0 + ch * 8;
                const uint32_t dB = so + ST_B_HI + row * 80 + ch * 16;
                CP_ASYNC16(dB, Bhi_ + go);
                CP_ASYNC16(dB + (ST_B_LO - ST_B_HI), Blo_ + go);
            }
        } else {
#pragma unroll
            for (int i = 0; i < 2; i++) {
                const int s = i * 256 + tid;
                const int k = s >> 4, ch = s & 15;
                const size_t go = (size_t)(k0 + k) * TD + n0 + ch * 8;
                const uint32_t dB = so + ST_B_HI + k * 256 + ((ch ^ (k & 7)) * 16);
                CP_ASYNC16(dB, Bhi_ + go);
                CP_ASYNC16(dB + (ST_B_LO - ST_B_HI), Blo_ + go);
            }
        }
    };

    float acc[2][8][4] = {};

    // preload 3 chunks
#pragma unroll
    for (int c = 0; c < 3; c++) { load_chunk(c, c); CP_COMMIT(); }

#pragma unroll 1
    for (int c = 0; c < nch; c++) {
        CP_WAITG2();            // chunk c landed
        __syncthreads();        // stage (c+3)&3 = (c-1)&3 fully consumed
        if (c + 3 < nch) load_chunk(c + 3, (c + 3) & 3);
        CP_COMMIT();

        const uint32_t so = sbase + (c & 3) * STAGE_SZ;
        const uint32_t sA = so + ST_A_HI;
        const uint32_t sB = so + ST_B_HI;

        // ---- load ALL fragments for both ks before any mma ----
        uint32_t ahi[2][2][4], alo[2][2][4], bhi[2][4][4], blo[2][4][4];
#pragma unroll
        for (int ks = 0; ks < 2; ks++) {
#pragma unroll
            for (int mt = 0; mt < 2; mt++) {
                const uint32_t ad = sA + (wm + mt * 16 + (lane & 15)) * 80
                                       + (ks * 2 + (lane >> 4)) * 16;
                ldsm_x4(ahi[ks][mt], ad);
                ldsm_x4(alo[ks][mt], ad + (ST_A_LO - ST_A_HI));
            }
            if (MODE != 2) {
#pragma unroll
                for (int bp = 0; bp < 4; bp++) {
                    const int nt = bp * 2 + (lane >> 4);
                    const uint32_t bd = sB + (wn + nt * 8 + (lane & 7)) * 80
                                           + (ks * 2 + ((lane >> 3) & 1)) * 16;
                    ldsm_x4(bhi[ks][bp], bd);
                    ldsm_x4(blo[ks][bp], bd + (ST_B_LO - ST_B_HI));
                }
            } else {
                const int k = ks * 16 + (lane & 15);
#pragma unroll
                for (int bp = 0; bp < 4; bp++) {
                    const int cch = (wn >> 3) + bp * 2 + (lane >> 4);
                    const uint32_t bd = sB + k * 256 + ((cch ^ (k & 7)) * 16);
                    ldsm_x4_t(bhi[ks][bp], bd);
                    ldsm_x4_t(blo[ks][bp], bd + (ST_B_LO - ST_B_HI));
                }
            }
        }

        // ---- 192 mma; independent of the later-ks ldsm above, so ptxas can
        //      interleave issue and keep the tensor pipe fed ----
#pragma unroll
        for (int ks = 0; ks < 2; ks++) {
#pragma unroll
            for (int mt = 0; mt < 2; mt++)
#pragma unroll
                for (int bp = 0; bp < 4; bp++)
#pragma unroll
                    for (int h = 0; h < 2; h++)
                        mma_bf16(acc[mt][bp * 2 + h], ahi[ks][mt], &bhi[ks][bp][h * 2]);
#pragma unroll
            for (int mt = 0; mt < 2; mt++)
#pragma unroll
                for (int bp = 0; bp < 4; bp++)
#pragma unroll
                    for (int h = 0; h < 2; h++)
                        mma_bf16(acc[mt][bp * 2 + h], ahi[ks][mt], &blo[ks][bp][h * 2]);
#pragma unroll
            for (int mt = 0; mt < 2; mt++)
#pragma unroll
                for (int bp = 0; bp < 4; bp++)
#pragma unroll
                    for (int h = 0; h < 2; h++)
                        mma_bf16(acc[mt][bp * 2 + h], alo[ks][mt], &bhi[ks][bp][h * 2]);
        }
    }

    // ---- Epilogue (register -> gmem, no smem) ----
    if (MODE == 0) {
        const int group = n0 >> 10;
        const int pair = group >> 1, colbase = (group & 1) << 10;
        __nv_bfloat16* Dh = (pair == 0) ? g_Qhi : (pair == 1) ? g_Khi : g_Vhi;
        __nv_bfloat16* Dl = (pair == 0) ? g_Qlo : (pair == 1) ? g_Klo : g_Vlo;
        const int nbase = colbase + (n0 & 1023) + wn;
#pragma unroll
        for (int mt = 0; mt < 2; mt++)
#pragma unroll
            for (int nt = 0; nt < 8; nt++) {
                const int col = nbase + nt * 8 + tc * 2;
#pragma unroll
                for (int h = 0; h < 2; h++) {
                    const int row = m0 + wm + mt * 16 + tr + h * 8;
                    const float v0 = acc[mt][nt][h * 2 + 0];
                    const float v1 = acc[mt][nt][h * 2 + 1];
                    float h0, h1, l0, l1;
                    split_bf(v0, h0, l0); split_bf(v1, h1, l1);
                    const size_t o = (size_t)row * TD + col;
                    *(uint32_t*)(Dh + o) = pack2(h0, h1);
                    *(uint32_t*)(Dl + o) = pack2(l0, l1);
                }
            }
    } else if (MODE == 1) {
        const float scale = 0.03125f;  // 1024^-0.5
        float* C = g_P + (size_t)b * S_ * S_;
#pragma unroll
        for (int mt = 0; mt < 2; mt++)
#pragma unroll
            for (int nt = 0; nt < 8; nt++) {
                const int col = n0 + wn + nt * 8 + tc * 2;
#pragma unroll
                for (int h = 0; h < 2; h++) {
                    const int row = m0 + wm + mt * 16 + tr + h * 8;
                    float2 v = make_float2(acc[mt][nt][h * 2 + 0] * scale,
                                           acc[mt][nt][h * 2 + 1] * scale);
                    *(float2*)(C + (size_t)row * S_ + col) = v;
                }
            }
    } else {
#pragma unroll
        for (int mt = 0; mt < 2; mt++)
#pragma unroll
            for (int nt = 0; nt < 8; nt++) {
                const int n = n0 + wn + nt * 8 + tc * 2;
                const int part = n >> 10, d = n & 1023;
#pragma unroll
                for (int h = 0; h < 2; h++) {
                    const int s = m0 + wm + mt * 16 + tr + h * 8;
                    float2 v = make_float2(acc[mt][nt][h * 2 + 0],
                                           acc[mt][nt][h * 2 + 1]);
                    *(float2*)(outp + (((size_t)part * B_ + b) * S_ + s) * D_ + d) = v;
                }
            }
    }
}

// ---------------------------------------------------------------------------
// Causal row softmax on fp32 g_P; writes bf16 hi/lo split (zero past diag).
// ---------------------------------------------------------------------------
__global__ void __launch_bounds__(256) softmax_split_kernel() {
    const int row = blockIdx.x;            // b*S + i
    const int i = row & (S_ - 1);
    const float* p = g_P + (size_t)row * S_;
    __nv_bfloat16* ph = g_Phi + (size_t)row * S_;
    __nv_bfloat16* pl = g_Plo + (size_t)row * S_;
    const int L = i + 1;
    const int tid = threadIdx.x;

    float v[8];
    float tmax = -3.0e38f;
#pragma unroll
    for (int r = 0; r < 8; r++) {
        const int j = r * 256 + tid;
        if (j < L) { v[r] = p[j]; tmax = fmaxf(tmax, v[r]); }
    }
    __shared__ float red[256];
    red[tid] = tmax; __syncthreads();
    for (int s = 128; s > 0; s >>= 1) {
        if (tid < s) red[tid] = fmaxf(red[tid], red[tid + s]);
        __syncthreads();
    }
    const float mx = red[0];
    __syncthreads();

    float tsum = 0.0f;
#pragma unroll
    for (int r = 0; r < 8; r++) {
        const int j = r * 256 + tid;
        if (j < L) { v[r] = __expf(v[r] - mx); tsum += v[r]; }
    }
    red[tid] = tsum; __syncthreads();
    for (int s = 128; s > 0; s >>= 1) {
        if (tid < s) red[tid] += red[tid + s];
        __syncthreads();
    }
    const float inv = 1.0f / red[0];

#pragma unroll
    for (int r = 0; r < 8; r++) {
        const int j = r * 256 + tid;
        float hv = 0.0f, lv = 0.0f;
        if (j < L) {
            const float pv = v[r] * inv;
            split_bf(pv, hv, lv);
        }
        ph[j] = __float2bfloat16(hv);
        pl[j] = __float2bfloat16(lv);
    }
}

// ---------------------------------------------------------------------------
extern "C" void kernel_launch(void* const* d_in, const int* in_sizes, int n_in,
                              void* d_out, int out_size) {
    const float* zr  = (const float*)d_in[0];
    const float* zi  = (const float*)d_in[1];
    const float* wqr = (const float*)d_in[2];
    const float* wqi = (const float*)d_in[3];
    const float* wkr = (const float*)d_in[4];
    const float* wki = (const float*)d_in[5];
    const float* wvr = (const float*)d_in[6];
    const float* wvi = (const float*)d_in[7];
    // d_in[8] = tril mask — causal by construction; unused.
    float* out = (float*)d_out;

    cudaFuncSetAttribute(gemm_kernel<0>, cudaFuncAttributeMaxDynamicSharedMemorySize, SMEM_TOTAL);
    cudaFuncSetAttribute(gemm_kernel<1>, cudaFuncAttributeMaxDynamicSharedMemorySize, SMEM_TOTAL);
    cudaFuncSetAttribute(gemm_kernel<2>, cudaFuncAttributeMaxDynamicSharedMemorySize, SMEM_TOTAL);

    split_z_kernel<<<(M_ * TD / 4) / 256, 256>>>(zr, zi);
    build_w_kernel<<<(3 * TD * TD / 4) / 256, 256>>>(wqr, wqi, wkr, wki, wvr, wvi);
    gemm_kernel<0><<<dim3(3 * TD / BN, M_ / BM), 256, SMEM_TOTAL>>>(nullptr);
    gemm_kernel<1><<<dim3(136, 1, B_), 256, SMEM_TOTAL>>>(nullptr);   // lower-tri blocks
    softmax_split_kernel<<<B_ * S_, 256>>>();
    gemm_kernel<2><<<dim3(TD / BN, S_ / BM, B_), 256, SMEM_TOTAL>>>(out);
}

// round 15
// speedup vs baseline: 1.0091x; 1.0091x over previous
#include <cuda_runtime.h>
#include <cuda_bf16.h>
#include <cstdint>

// ComplexAttention B=4, S=2048, DIM=1024 — split-bf16 mma.sync tensor-core port.
// R13: 512-thread CTA (16 warps, 32x32 warp tile) -> 4 warps/SMSP to cover
// ldsm/HMMA latency (tensor pipe was stuck at 50% with 2 warps/SMSP).
#define B_ 4
#define S_ 2048
#define D_ 1024
#define M_ (B_ * S_)   // 8192
#define TD 2048        // 2*D

// GEMM tiling
#define BM 128
#define BN 128
#define BK 32
#define NTHREADS 512
#define NSTAGE 4
#define ST_A_HI 0
#define ST_A_LO 10240
#define ST_B_HI 20480
#define ST_B_LO 30720
#define STAGE_SZ 40960
#define SMEM_TOTAL (NSTAGE * STAGE_SZ)   // 163840

// ---------------------------------------------------------------------------
// Scratch (__device__ globals; allocation-free rule)
// ---------------------------------------------------------------------------
__device__ __nv_bfloat16 g_Zhi[(size_t)M_ * TD];
__device__ __nv_bfloat16 g_Zlo[(size_t)M_ * TD];
__device__ __nv_bfloat16 g_Whi[(size_t)3 * TD * TD];   // 6144 x 2048
__device__ __nv_bfloat16 g_Wlo[(size_t)3 * TD * TD];
__device__ __nv_bfloat16 g_Qhi[(size_t)M_ * TD];
__device__ __nv_bfloat16 g_Qlo[(size_t)M_ * TD];
__device__ __nv_bfloat16 g_Khi[(size_t)M_ * TD];
__device__ __nv_bfloat16 g_Klo[(size_t)M_ * TD];
__device__ __nv_bfloat16 g_Vhi[(size_t)M_ * TD];       // natural [b*t][n]
__device__ __nv_bfloat16 g_Vlo[(size_t)M_ * TD];
__device__ float         g_P  [(size_t)B_ * S_ * S_];
__device__ __nv_bfloat16 g_Phi[(size_t)B_ * S_ * S_];
__device__ __nv_bfloat16 g_Plo[(size_t)B_ * S_ * S_];

// ---------------------------------------------------------------------------
// PTX helpers (sm_80-class only)
// ---------------------------------------------------------------------------
__device__ __forceinline__ uint32_t smem_u32(const void* p) {
    uint32_t a;
    asm("{ .reg .u64 t; cvta.to.shared.u64 t, %1; cvt.u32.u64 %0, t; }" : "=r"(a) : "l"(p));
    return a;
}
__device__ __forceinline__ void ldsm_x4(uint32_t* r, uint32_t addr) {
    asm volatile("ldmatrix.sync.aligned.m8n8.x4.shared.b16 {%0,%1,%2,%3}, [%4];"
        : "=r"(r[0]), "=r"(r[1]), "=r"(r[2]), "=r"(r[3]) : "r"(addr));
}
__device__ __forceinline__ void ldsm_x4_t(uint32_t* r, uint32_t addr) {
    asm volatile("ldmatrix.sync.aligned.m8n8.x4.trans.shared.b16 {%0,%1,%2,%3}, [%4];"
        : "=r"(r[0]), "=r"(r[1]), "=r"(r[2]), "=r"(r[3]) : "r"(addr));
}
__device__ __forceinline__ void mma_bf16(float* d, const uint32_t* a, const uint32_t* b) {
    asm volatile(
        "mma.sync.aligned.m16n8k16.row.col.f32.bf16.bf16.f32 "
        "{%0,%1,%2,%3}, {%4,%5,%6,%7}, {%8,%9}, {%0,%1,%2,%3};"
        : "+f"(d[0]), "+f"(d[1]), "+f"(d[2]), "+f"(d[3])
        : "r"(a[0]), "r"(a[1]), "r"(a[2]), "r"(a[3]), "r"(b[0]), "r"(b[1]));
}
#define CP_ASYNC16(dst, src) \
    asm volatile("cp.async.cg.shared.global [%0], [%1], 16;" :: "r"(dst), "l"(src) : "memory")
#define CP_COMMIT() asm volatile("cp.async.commit_group;" ::: "memory")
#define CP_WAITG2() asm volatile("cp.async.wait_group 2;" ::: "memory")

__device__ __forceinline__ uint32_t pack2(float a, float b) {
    uint16_t la = __bfloat16_as_ushort(__float2bfloat16(a));
    uint16_t lb = __bfloat16_as_ushort(__float2bfloat16(b));
    return (uint32_t)la | ((uint32_t)lb << 16);
}
__device__ __forceinline__ void split_bf(float x, float& h, float& l) {
    h = __bfloat162float(__float2bfloat16(x));
    l = x - h;
}

// ---------------------------------------------------------------------------
// Prep 1: Zcat = [zr|zi] split to bf16 hi/lo.
// ---------------------------------------------------------------------------
__global__ void __launch_bounds__(256) split_z_kernel(const float* __restrict__ zr,
                                                      const float* __restrict__ zi) {
    const int idx = blockIdx.x * 256 + threadIdx.x;
    const int m = idx >> 9, c4 = idx & 511;
    const float* src = (c4 < 256) ? (zr + (size_t)m * D_ + c4 * 4)
                                  : (zi + (size_t)m * D_ + (c4 - 256) * 4);
    float4 x = *(const float4*)src;
    float h0, h1, h2, h3, l0, l1, l2, l3;
    split_bf(x.x, h0, l0); split_bf(x.y, h1, l1);
    split_bf(x.z, h2, l2); split_bf(x.w, h3, l3);
    const size_t o = (size_t)m * TD + c4 * 4;
    *(uint2*)(g_Zhi + o) = make_uint2(pack2(h0, h1), pack2(h2, h3));
    *(uint2*)(g_Zlo + o) = make_uint2(pack2(l0, l1), pack2(l2, l3));
}

// ---------------------------------------------------------------------------
// Prep 2: Wcat [6144 x 2048] with signs, split bf16 hi/lo.
// ---------------------------------------------------------------------------
__global__ void __launch_bounds__(256) build_w_kernel(
    const float* __restrict__ wqr, const float* __restrict__ wqi,
    const float* __restrict__ wkr, const float* __restrict__ wki,
    const float* __restrict__ wvr, const float* __restrict__ wvi) {
    const int idx = blockIdx.x * 256 + threadIdx.x;
    const int gn = idx >> 9, c4 = idx & 511;
    const int pair = gn >> 11, is_imag = (gn >> 10) & 1, nn = gn & 1023;
    const float* wr = (pair == 0) ? wqr : (pair == 1) ? wkr : wvr;
    const float* wi = (pair == 0) ? wqi : (pair == 1) ? wki : wvi;
    const float* wl = is_imag ? wi : wr;
    const float* wh = is_imag ? wr : wi;
    float4 x;
    if (c4 < 256) {
        x = *(const float4*)(wl + (size_t)nn * D_ + c4 * 4);
    } else {
        x = *(const float4*)(wh + (size_t)nn * D_ + (c4 - 256) * 4);
        const float s = is_imag ? 1.0f : -1.0f;
        x.x *= s; x.y *= s; x.z *= s; x.w *= s;
    }
    float h0, h1, h2, h3, l0, l1, l2, l3;
    split_bf(x.x, h0, l0); split_bf(x.y, h1, l1);
    split_bf(x.z, h2, l2); split_bf(x.w, h3, l3);
    const size_t o = (size_t)gn * TD + c4 * 4;
    *(uint2*)(g_Whi + o) = make_uint2(pack2(h0, h1), pack2(h2, h3));
    *(uint2*)(g_Wlo + o) = make_uint2(pack2(l0, l1), pack2(l2, l3));
}

// ---------------------------------------------------------------------------
// Split-bf16 tensor-core GEMM. MODE: 0=proj  1=scores  2=PV
// 512 threads, 16 warps in 4x4 grid, warp tile 32x32 (4 warps/SMSP).
// 4-stage cp.async ring; one barrier per chunk.
// ---------------------------------------------------------------------------
template <int MODE>
__global__ void __launch_bounds__(NTHREADS, 1)
gemm_kernel(float* __restrict__ outp) {
    extern __shared__ char smem[];
    const uint32_t sbase = smem_u32(smem);
    const int tid = threadIdx.x;
    const int wid = tid >> 5, lane = tid & 31;
    const int wm = (wid & 3) * 32;        // warp row base within tile
    const int wn = (wid >> 2) * 32;       // warp col base within tile
    const int tr = lane >> 2, tc = lane & 3;

    int m0, n0, kend, b = 0;
    const __nv_bfloat16 *Ahi_, *Alo_, *Bhi_, *Blo_;
    if (MODE == 0) {
        m0 = blockIdx.y * BM; n0 = blockIdx.x * BN; kend = TD;
        Ahi_ = g_Zhi; Alo_ = g_Zlo; Bhi_ = g_Whi; Blo_ = g_Wlo;
    } else if (MODE == 1) {
        b = blockIdx.z;
        const int x = blockIdx.x;   // triangular: x -> (r, c), c <= r
        int r = (int)((sqrtf(8.0f * x + 1.0f) - 1.0f) * 0.5f);
        while ((r + 1) * (r + 2) / 2 <= x) r++;
        while (r * (r + 1) / 2 > x) r--;
        m0 = r * BM; n0 = (x - r * (r + 1) / 2) * BN;
        kend = TD;
        Ahi_ = g_Qhi + (size_t)b * S_ * TD; Alo_ = g_Qlo + (size_t)b * S_ * TD;
        Bhi_ = g_Khi + (size_t)b * S_ * TD; Blo_ = g_Klo + (size_t)b * S_ * TD;
    } else {
        b = blockIdx.z; m0 = blockIdx.y * BM; n0 = blockIdx.x * BN;
        kend = m0 + BM;                   // P zero beyond diagonal
        Ahi_ = g_Phi + (size_t)b * S_ * S_; Alo_ = g_Plo + (size_t)b * S_ * S_;
        Bhi_ = g_Vhi + (size_t)b * S_ * TD; Blo_ = g_Vlo + (size_t)b * S_ * TD;
    }

    const int nch = kend / BK;   // >= 4 in all modes

    // ---- async chunk loader: 512 threads, 1 cp.async per buffer each ----
    auto load_chunk = [&](int c, int st) {
        const int k0 = c * BK;
        const uint32_t so = sbase + st * STAGE_SZ;
        {
            const int row = tid >> 2, ch = tid & 3;       // 128 x 4
            const size_t go = (size_t)(m0 + row) * TD + k0 + ch * 8;
            const uint32_t dA = so + ST_A_HI + row * 80 + ch * 16;
            CP_ASYNC16(dA, Ahi_ + go);
            CP_ASYNC16(dA + (ST_A_LO - ST_A_HI), Alo_ + go);
        }
        if (MODE != 2) {
            const int row = tid >> 2, ch = tid & 3;
            const size_t go = (size_t)(n0 + row) * TD + k0 + ch * 8;
            const uint32_t dB = so + ST_B_HI + row * 80 + ch * 16;
            CP_ASYNC16(dB, Bhi_ + go);
            CP_ASYNC16(dB + (ST_B_LO - ST_B_HI), Blo_ + go);
        } else {
            const int k = tid >> 4, ch = tid & 15;        // 32 x 16
            const size_t go = (size_t)(k0 + k) * TD + n0 + ch * 8;
            const uint32_t dB = so + ST_B_HI + k * 256 + ((ch ^ (k & 7)) * 16);
            CP_ASYNC16(dB, Bhi_ + go);
            CP_ASYNC16(dB + (ST_B_LO - ST_B_HI), Blo_ + go);
        }
    };

    float acc[2][4][4] = {};   // 2 m16 x 4 n8 x 4

    // preload 3 chunks
#pragma unroll
    for (int c = 0; c < 3; c++) { load_chunk(c, c); CP_COMMIT(); }

#pragma unroll 1
    for (int c = 0; c < nch; c++) {
        CP_WAITG2();            // chunk c landed
        __syncthreads();        // stage (c+3)&3 = (c-1)&3 fully consumed
        if (c + 3 < nch) load_chunk(c + 3, (c + 3) & 3);
        CP_COMMIT();

        const uint32_t so = sbase + (c & 3) * STAGE_SZ;
        const uint32_t sA = so + ST_A_HI;
        const uint32_t sB = so + ST_B_HI;

#pragma unroll
        for (int ks = 0; ks < 2; ks++) {
            uint32_t ahi[2][4], alo[2][4], bhi[2][4], blo[2][4];
#pragma unroll
            for (int mt = 0; mt < 2; mt++) {
                const uint32_t ad = sA + (wm + mt * 16 + (lane & 15)) * 80
                                       + (ks * 2 + (lane >> 4)) * 16;
                ldsm_x4(ahi[mt], ad);
                ldsm_x4(alo[mt], ad + (ST_A_LO - ST_A_HI));
            }
            if (MODE != 2) {
#pragma unroll
                for (int bp = 0; bp < 2; bp++) {
                    const int nt = bp * 2 + (lane >> 4);
                    const uint32_t bd = sB + (wn + nt * 8 + (lane & 7)) * 80
                                           + (ks * 2 + ((lane >> 3) & 1)) * 16;
                    ldsm_x4(bhi[bp], bd);
                    ldsm_x4(blo[bp], bd + (ST_B_LO - ST_B_HI));
                }
            } else {
                const int k = ks * 16 + (lane & 15);
#pragma unroll
                for (int bp = 0; bp < 2; bp++) {
                    const int cch = (wn >> 3) + bp * 2 + (lane >> 4);
                    const uint32_t bd = sB + k * 256 + ((cch ^ (k & 7)) * 16);
                    ldsm_x4_t(bhi[bp], bd);
                    ldsm_x4_t(blo[bp], bd + (ST_B_LO - ST_B_HI));
                }
            }
            // phase 1: Ahi * Bhi
#pragma unroll
            for (int mt = 0; mt < 2; mt++)
#pragma unroll
                for (int bp = 0; bp < 2; bp++)
#pragma unroll
                    for (int h = 0; h < 2; h++)
                        mma_bf16(acc[mt][bp * 2 + h], ahi[mt], &bhi[bp][h * 2]);
            // phase 2: Ahi * Blo
#pragma unroll
            for (int mt = 0; mt < 2; mt++)
#pragma unroll
                for (int bp = 0; bp < 2; bp++)
#pragma unroll
                    for (int h = 0; h < 2; h++)
                        mma_bf16(acc[mt][bp * 2 + h], ahi[mt], &blo[bp][h * 2]);
            // phase 3: Alo * Bhi
#pragma unroll
            for (int mt = 0; mt < 2; mt++)
#pragma unroll
                for (int bp = 0; bp < 2; bp++)
#pragma unroll
                    for (int h = 0; h < 2; h++)
                        mma_bf16(acc[mt][bp * 2 + h], alo[mt], &bhi[bp][h * 2]);
        }
    }

    // ---- Epilogue (register -> gmem, no smem) ----
    if (MODE == 0) {
        const int group = n0 >> 10;
        const int pair = group >> 1, colbase = (group & 1) << 10;
        __nv_bfloat16* Dh = (pair == 0) ? g_Qhi : (pair == 1) ? g_Khi : g_Vhi;
        __nv_bfloat16* Dl = (pair == 0) ? g_Qlo : (pair == 1) ? g_Klo : g_Vlo;
        const int nbase = colbase + (n0 & 1023) + wn;
#pragma unroll
        for (int mt = 0; mt < 2; mt++)
#pragma unroll
            for (int nt = 0; nt < 4; nt++) {
                const int col = nbase + nt * 8 + tc * 2;
#pragma unroll
                for (int h = 0; h < 2; h++) {
                    const int row = m0 + wm + mt * 16 + tr + h * 8;
                    const float v0 = acc[mt][nt][h * 2 + 0];
                    const float v1 = acc[mt][nt][h * 2 + 1];
                    float h0, h1, l0, l1;
                    split_bf(v0, h0, l0); split_bf(v1, h1, l1);
                    const size_t o = (size_t)row * TD + col;
                    *(uint32_t*)(Dh + o) = pack2(h0, h1);
                    *(uint32_t*)(Dl + o) = pack2(l0, l1);
                }
            }
    } else if (MODE == 1) {
        const float scale = 0.03125f;  // 1024^-0.5
        float* C = g_P + (size_t)b * S_ * S_;
#pragma unroll
        for (int mt = 0; mt < 2; mt++)
#pragma unroll
            for (int nt = 0; nt < 4; nt++) {
                const int col = n0 + wn + nt * 8 + tc * 2;
#pragma unroll
                for (int h = 0; h < 2; h++) {
                    const int row = m0 + wm + mt * 16 + tr + h * 8;
                    float2 v = make_float2(acc[mt][nt][h * 2 + 0] * scale,
                                           acc[mt][nt][h * 2 + 1] * scale);
                    *(float2*)(C + (size_t)row * S_ + col) = v;
                }
            }
    } else {
#pragma unroll
        for (int mt = 0; mt < 2; mt++)
#pragma unroll
            for (int nt = 0; nt < 4; nt++) {
                const int n = n0 + wn + nt * 8 + tc * 2;
                const int part = n >> 10, d = n & 1023;
#pragma unroll
                for (int h = 0; h < 2; h++) {
                    const int s = m0 + wm + mt * 16 + tr + h * 8;
                    float2 v = make_float2(acc[mt][nt][h * 2 + 0],
                                           acc[mt][nt][h * 2 + 1]);
                    *(float2*)(outp + (((size_t)part * B_ + b) * S_ + s) * D_ + d) = v;
                }
            }
    }
}

// ---------------------------------------------------------------------------
// Causal row softmax on fp32 g_P; writes bf16 hi/lo split (zero past diag).
// ---------------------------------------------------------------------------
__global__ void __launch_bounds__(256) softmax_split_kernel() {
    const int row = blockIdx.x;            // b*S + i
    const int i = row & (S_ - 1);
    const float* p = g_P + (size_t)row * S_;
    __nv_bfloat16* ph = g_Phi + (size_t)row * S_;
    __nv_bfloat16* pl = g_Plo + (size_t)row * S_;
    const int L = i + 1;
    const int tid = threadIdx.x;

    float v[8];
    float tmax = -3.0e38f;
#pragma unroll
    for (int r = 0; r < 8; r++) {
        const int j = r * 256 + tid;
        if (j < L) { v[r] = p[j]; tmax = fmaxf(tmax, v[r]); }
    }
    __shared__ float red[256];
    red[tid] = tmax; __syncthreads();
    for (int s = 128; s > 0; s >>= 1) {
        if (tid < s) red[tid] = fmaxf(red[tid], red[tid + s]);
        __syncthreads();
    }
    const float mx = red[0];
    __syncthreads();

    float tsum = 0.0f;
#pragma unroll
    for (int r = 0; r < 8; r++) {
        const int j = r * 256 + tid;
        if (j < L) { v[r] = __expf(v[r] - mx); tsum += v[r]; }
    }
    red[tid] = tsum; __syncthreads();
    for (int s = 128; s > 0; s >>= 1) {
        if (tid < s) red[tid] += red[tid + s];
        __syncthreads();
    }
    const float inv = 1.0f / red[0];

#pragma unroll
    for (int r = 0; r < 8; r++) {
        const int j = r * 256 + tid;
        float hv = 0.0f, lv = 0.0f;
        if (j < L) {
            const float pv = v[r] * inv;
            split_bf(pv, hv, lv);
        }
        ph[j] = __float2bfloat16(hv);
        pl[j] = __float2bfloat16(lv);
    }
}

// ---------------------------------------------------------------------------
extern "C" void kernel_launch(void* const* d_in, const int* in_sizes, int n_in,
                              void* d_out, int out_size) {
    const float* zr  = (const float*)d_in[0];
    const float* zi  = (const float*)d_in[1];
    const float* wqr = (const float*)d_in[2];
    const float* wqi = (const float*)d_in[3];
    const float* wkr = (const float*)d_in[4];
    const float* wki = (const float*)d_in[5];
    const float* wvr = (const float*)d_in[6];
    const float* wvi = (const float*)d_in[7];
    // d_in[8] = tril mask — causal by construction; unused.
    float* out = (float*)d_out;

    cudaFuncSetAttribute(gemm_kernel<0>, cudaFuncAttributeMaxDynamicSharedMemorySize, SMEM_TOTAL);
    cudaFuncSetAttribute(gemm_kernel<1>, cudaFuncAttributeMaxDynamicSharedMemorySize, SMEM_TOTAL);
    cudaFuncSetAttribute(gemm_kernel<2>, cudaFuncAttributeMaxDynamicSharedMemorySize, SMEM_TOTAL);

    split_z_kernel<<<(M_ * TD / 4) / 256, 256>>>(zr, zi);
    build_w_kernel<<<(3 * TD * TD / 4) / 256, 256>>>(wqr, wqi, wkr, wki, wvr, wvi);
    gemm_kernel<0><<<dim3(3 * TD / BN, M_ / BM), NTHREADS, SMEM_TOTAL>>>(nullptr);
    gemm_kernel<1><<<dim3(136, 1, B_), NTHREADS, SMEM_TOTAL>>>(nullptr);   // lower-tri
    softmax_split_kernel<<<B_ * S_, 256>>>();
    gemm_kernel<2><<<dim3(TD / BN, S_ / BM, B_), NTHREADS, SMEM_TOTAL>>>(out);
}